// round 16
// baseline (speedup 1.0000x reference)
#include <cuda_runtime.h>
#include <math.h>

#define DD 128
#define WIN 15
#define WW (2*WIN+1)          // 31
#define CR 16                 // central rows per band block
#define LR (CR + 4*WIN)       // 76 loaded rows   [i0-30, i0+46)
#define DR (CR + 2*WIN)       // 46 dinv rows     [i0-15, i0+31)
#define SR (CR + 3*WIN)       // 61 fwd-dot rows  [i0-30, i0+31)
#define RPAD 132
#define RP4  (RPAD/4)         // 33
#define SMEM_FLOATS (LR*RPAD + SR*WIN + CR*WW + DR + LR)
#define SMEM_BYTES  (SMEM_FLOATS * 4)   // ~46.3 KB

__device__ __forceinline__ void stg256_cs(float* p, const float4& a, const float4& b) {
    asm volatile("st.global.cs.v8.f32 [%0], {%1,%2,%3,%4,%5,%6,%7,%8};"
                 :: "l"(p),
                    "f"(a.x), "f"(a.y), "f"(a.z), "f"(a.w),
                    "f"(b.x), "f"(b.y), "f"(b.z), "f"(b.w)
                 : "memory");
}

// fast acos: Abramowitz-Stegun 4.4.45, |err| <= 6.7e-5 rad
__device__ __forceinline__ float angular_weight(float c) {
    float ax = fabsf(c);
    float s = sqrtf(fmaxf(1.f - ax, 0.f));
    float p = s * (1.5707288f + ax * (-0.2121144f + ax * (0.0742610f - ax * 0.0187293f)));
    float ac = (c >= 0.f) ? p : (3.14159265358979f - p);
    return 1.f - ac * 0.31830988618379067f;
}

__global__ __launch_bounds__(256)
void combined_kernel(const float* __restrict__ x,
                     const float* __restrict__ qmask,
                     const int* __restrict__ dia_len,
                     float* __restrict__ out,
                     int B, int S, int NSPK, int NBAND) {
    extern __shared__ float smem[];
    int lane = threadIdx.x & 31;
    int warp = threadIdx.x >> 5;

    // ================= zero role: bid >= NBAND =================
    if ((int)blockIdx.x >= NBAND) {
        int row = blockIdx.x - NBAND;          // b*S + i
        int i = row % S;
        float* orow = out + (size_t)row * S;
        int clo = max(i - WIN, 0) >> 3;
        int chi = min(i + WIN, S - 1) >> 3;
        const float4 z = make_float4(0.f, 0.f, 0.f, 0.f);
        int nch = S >> 3;
        for (int c = threadIdx.x; c < nch; c += blockDim.x) {
            if (c < clo || c > chi)
                stg256_cs(orow + (c << 3), z, z);
        }
        return;
    }

    // ================= band role: self-contained, writes band chunks =================
    float* sx    = smem;                       // LR * RPAD normalized rows
    float* sdot  = sx + LR * RPAD;             // SR * 15 forward dots
    float* sband = sdot + SR * WIN;            // CR * 31 band values
    float* sdinv = sband + CR * WW;            // DR
    int*   sspk  = (int*)(sdinv + DR);         // LR

    int nc = S / CR;                           // band chunks per batch
    int b  = blockIdx.x / nc;
    int i0 = (blockIdx.x % nc) * CR;
    int base = b * S;
    int len = dia_len[b];
    int g0 = i0 - 2 * WIN;

    float4* sx4 = (float4*)sx;
    const float4* x4g = (const float4*)(x + (size_t)base * DD);

    // ---- Phase A: load + normalize LR rows (8 thr/row, shfl warp-converged) ----
    {
        int sub = threadIdx.x & 7;
        int rbase = threadIdx.x >> 3;          // 0..31
#pragma unroll
        for (int pass = 0; pass < 3; pass++) {
            int r = pass * 32 + rbase;         // 0..95
            int gr = g0 + r;
            bool inb = (r < LR) && (gr >= 0) && (gr < S);
            float4 v[4];
            float ss = 0.f;
            if (inb) {
#pragma unroll
                for (int k = 0; k < 4; k++) {
                    v[k] = x4g[(size_t)gr * (DD/4) + sub * 4 + k];
                    ss += v[k].x * v[k].x + v[k].y * v[k].y
                        + v[k].z * v[k].z + v[k].w * v[k].w;
                }
            } else {
#pragma unroll
                for (int k = 0; k < 4; k++) v[k] = make_float4(0.f, 0.f, 0.f, 0.f);
            }
#pragma unroll
            for (int off = 4; off; off >>= 1)
                ss += __shfl_xor_sync(0xffffffffu, ss, off);
            float inv = 1.f / fmaxf(sqrtf(ss), 1e-8f);
            if (r < LR) {
#pragma unroll
                for (int k = 0; k < 4; k++) {
                    v[k].x *= inv; v[k].y *= inv; v[k].z *= inv; v[k].w *= inv;
                    sx4[r * RP4 + sub * 4 + k] = v[k];
                }
            }
        }
        if (threadIdx.x < LR) {
            int gr = g0 + threadIdx.x;
            int bi = -1;
            if (gr >= 0 && gr < S) {
                const float* q = qmask + ((size_t)gr * B + b) * NSPK;
                float best = q[0]; bi = 0;
                for (int k = 1; k < NSPK; k++) {
                    float vq = q[k];
                    if (vq > best) { best = vq; bi = k; }   // JAX first-max
                }
            }
            sspk[threadIdx.x] = bi;
        }
    }
    __syncthreads();

    // ---- Phase B: forward dots. sdot[p][o] = dot(row p, row p+1+o) ----
    {
        int half = lane >> 4;
        int o = lane & 15;
#pragma unroll
        for (int it = 0; it < 4; it++) {
            int p = it * 16 + warp * 2 + half;     // 0..63
            bool act = (p < SR) && (o < 15);
            int pc  = act ? p : 0;
            int rjc = act ? (p + 1 + o) : 0;       // <= 75 < LR
            float dot = 0.f;
            const float4* xi4 = sx4 + pc * RP4;
            const float4* xj4 = sx4 + rjc * RP4;
#pragma unroll
            for (int k = 0; k < DD/4; k++) {
                float4 a4 = xi4[k];
                float4 b4 = xj4[k];
                dot += a4.x * b4.x + a4.y * b4.y + a4.z * b4.z + a4.w * b4.w;
            }
            if (act) sdot[p * WIN + o] = dot;
        }
    }
    __syncthreads();

    // ---- Phase C: deg/dinv for DR rows; band values for CR central rows ----
    {
#pragma unroll
        for (int it = 0; it < 6; it++) {
            int gl = it * 8 + warp;                // 0..47
            if (gl >= DR) continue;
            int g = i0 - WIN + gl;
            int sxr = gl + WIN;
            bool valid_i = (g >= 0) && (g < S) && (g < len);
            int spk_i = sspk[sxr];

            int j = g - WIN + lane;
            int sxj = gl + lane;                   // <= 45+31=76? gl<=45, lane<=30 used -> <=75 < LR
            bool inr = (lane < WW) && (j >= 0) && (j < S);

            float dot = 0.f;
            if (lane < WIN) {
                if (j >= 0) dot = sdot[(gl + lane) * WIN + (14 - lane)];  // row <= 59 < SR
            } else if (lane == WIN) {
                dot = 1.f;
            } else if (lane < WW) {
                dot = sdot[sxr * WIN + (lane - 16)];                      // row <= 60 < SR
            }

            bool valid_j = valid_i && inr && (j < len);
            bool same = valid_j && (sspk[sxj] == spk_i);
            int cnt = __popc(__ballot_sync(0xffffffffu, same));

            float a = 0.f;
            if (valid_j) {
                float c = fminf(fmaxf(dot, -1.f), 1.f);
                a = angular_weight(c) * ((cnt > 1 && same) ? 2.f : 1.f);
            }

            float deg = a;
#pragma unroll
            for (int off = 16; off; off >>= 1)
                deg += __shfl_xor_sync(0xffffffffu, deg, off);

            if (gl >= WIN && gl < WIN + CR && lane < WW)
                sband[(gl - WIN) * WW + lane] = a;
            if (lane == 0)
                sdinv[gl] = (deg > 0.f) ? rsqrtf(deg) : 1.f;
        }
    }
    __syncthreads();

    // ---- Phase D: write the CR band regions (disjoint 32B sectors vs zero role) ----
    {
#pragma unroll
        for (int it = 0; it < 2; it++) {
            int c = it * 8 + warp;                 // 0..15
            int i = i0 + c;
            int jstart = max(i - WIN, 0);
            int jend   = min(i + WIN, S - 1);
            int p0 = jstart & ~7;
            int p1 = (jend & ~7) + 7;
            float di = sdinv[c + WIN];
            float* orow = out + ((size_t)base + i) * S;
#pragma unroll
            for (int pass = 0; pass < 2; pass++) {
                int j2 = p0 + pass * 32 + lane;
                if (j2 <= p1) {
                    int d = j2 - (i - WIN);
                    float v = 0.f;
                    if (d >= 0 && d < WW)
                        v = sband[c * WW + d] * di * sdinv[c + d];
                    orow[j2] = v;
                }
            }
        }
    }
}

extern "C" void kernel_launch(void* const* d_in, const int* in_sizes, int n_in,
                              void* d_out, int out_size) {
    const float* x       = (const float*)d_in[0];
    const float* qmask   = (const float*)d_in[1];
    const int*   dia_len = (const int*)d_in[2];
    float* out = (float*)d_out;

    int B = in_sizes[2];
    int S = in_sizes[0] / (B * DD);
    int NSPK = in_sizes[1] / (B * S);
    int n = B * S;
    int NBAND = (S / CR) * B;                  // 1024

    static bool configured = false;
    if (!configured) {
        cudaFuncSetAttribute(combined_kernel,
                             cudaFuncAttributeMaxDynamicSharedMemorySize, SMEM_BYTES);
        configured = true;
    }

    // one grid: band blocks first (start immediately), zero blocks stream behind.
    // No inter-block dependencies anywhere; outputs are disjoint 32B sectors.
    combined_kernel<<<NBAND + n, 256, SMEM_BYTES>>>(x, qmask, dia_len, out,
                                                    B, S, NSPK, NBAND);
}

// round 17
// speedup vs baseline: 1.2615x; 1.2615x over previous
#include <cuda_runtime.h>
#include <cuda_fp16.h>
#include <math.h>

#define DD 128
#define WIN 15
#define WW (2*WIN+1)          // 31
#define CR 16                 // central rows per band block
#define LR (CR + 4*WIN)       // 76 loaded rows   [i0-30, i0+46)
#define DR (CR + 2*WIN)       // 46 dinv rows     [i0-15, i0+31)
#define SR (CR + 3*WIN)       // 61 fwd-dot rows  [i0-30, i0+31)
#define HR4 17                // uint4 (8 halves) per smem row incl. pad (272B/row)

__device__ __forceinline__ void stg256_cs(float* p, const float4& a, const float4& b) {
    asm volatile("st.global.cs.v8.f32 [%0], {%1,%2,%3,%4,%5,%6,%7,%8};"
                 :: "l"(p),
                    "f"(a.x), "f"(a.y), "f"(a.z), "f"(a.w),
                    "f"(b.x), "f"(b.y), "f"(b.z), "f"(b.w)
                 : "memory");
}

// fast acos: Abramowitz-Stegun 4.4.45, |err| <= 6.7e-5 rad
__device__ __forceinline__ float angular_weight(float c) {
    float ax = fabsf(c);
    float s = sqrtf(fmaxf(1.f - ax, 0.f));
    float p = s * (1.5707288f + ax * (-0.2121144f + ax * (0.0742610f - ax * 0.0187293f)));
    float ac = (c >= 0.f) ? p : (3.14159265358979f - p);
    return 1.f - ac * 0.31830988618379067f;
}

__global__ __launch_bounds__(256)
void combined_kernel(const float* __restrict__ x,
                     const float* __restrict__ qmask,
                     const int* __restrict__ dia_len,
                     float* __restrict__ out,
                     int B, int S, int NSPK, int NBAND) {
    // static smem (~26.8 KB) -> 8 blocks/SM, same as the thread-limit cap,
    // so the zero role keeps full occupancy.
    __shared__ __align__(16) uint4 sxh4[LR * HR4];    // fp16 normalized rows
    __shared__ float sdot[SR * WIN];                  // forward dots
    __shared__ float sband[CR * WW];
    __shared__ float sdinv[DR];
    __shared__ int   sspk[LR];

    int lane = threadIdx.x & 31;
    int warp = threadIdx.x >> 5;

    // ================= zero role =================
    if ((int)blockIdx.x >= NBAND) {
        int row = blockIdx.x - NBAND;          // b*S + i
        int i = row % S;
        float* orow = out + (size_t)row * S;
        int clo = max(i - WIN, 0) >> 3;
        int chi = min(i + WIN, S - 1) >> 3;
        const float4 z = make_float4(0.f, 0.f, 0.f, 0.f);
        int nch = S >> 3;
        for (int c = threadIdx.x; c < nch; c += blockDim.x) {
            if (c < clo || c > chi)
                stg256_cs(orow + (c << 3), z, z);
        }
        return;
    }

    // ================= band role: self-contained =================
    int nc = S / CR;
    int b  = blockIdx.x / nc;
    int i0 = (blockIdx.x % nc) * CR;
    int base = b * S;
    int len = dia_len[b];
    int g0 = i0 - 2 * WIN;

    const float4* x4g = (const float4*)(x + (size_t)base * DD);

    // ---- Phase A: load fp32, normalize, store fp16 (shfl warp-converged) ----
    {
        int sub = threadIdx.x & 7;             // 8 threads/row: halves [sub*16, sub*16+16)
        int rbase = threadIdx.x >> 3;
#pragma unroll
        for (int pass = 0; pass < 3; pass++) {
            int r = pass * 32 + rbase;         // 0..95
            int gr = g0 + r;
            bool inb = (r < LR) && (gr >= 0) && (gr < S);
            float4 v[4];
            float ss = 0.f;
            if (inb) {
#pragma unroll
                for (int k = 0; k < 4; k++) {
                    v[k] = x4g[(size_t)gr * (DD/4) + sub * 4 + k];
                    ss += v[k].x * v[k].x + v[k].y * v[k].y
                        + v[k].z * v[k].z + v[k].w * v[k].w;
                }
            } else {
#pragma unroll
                for (int k = 0; k < 4; k++) v[k] = make_float4(0.f, 0.f, 0.f, 0.f);
            }
#pragma unroll
            for (int off = 4; off; off >>= 1)
                ss += __shfl_xor_sync(0xffffffffu, ss, off);
            float inv = 1.f / fmaxf(sqrtf(ss), 1e-8f);
            if (r < LR) {
                uint4 h[2];
                __half2* hp = (__half2*)h;
#pragma unroll
                for (int k = 0; k < 4; k++) {
                    hp[2*k+0] = __floats2half2_rn(v[k].x * inv, v[k].y * inv);
                    hp[2*k+1] = __floats2half2_rn(v[k].z * inv, v[k].w * inv);
                }
                sxh4[r * HR4 + sub * 2 + 0] = h[0];
                sxh4[r * HR4 + sub * 2 + 1] = h[1];
            }
        }
        if (threadIdx.x < LR) {
            int gr = g0 + threadIdx.x;
            int bi = -1;
            if (gr >= 0 && gr < S) {
                const float* q = qmask + ((size_t)gr * B + b) * NSPK;
                float best = q[0]; bi = 0;
                for (int k = 1; k < NSPK; k++) {
                    float vq = q[k];
                    if (vq > best) { best = vq; bi = k; }   // JAX first-max
                }
            }
            sspk[threadIdx.x] = bi;
        }
    }
    __syncthreads();

    // ---- Phase B: forward dots. sdot[p][o] = dot(row p, row p+1+o) ----
    {
        int half = lane >> 4;
        int o = lane & 15;
#pragma unroll
        for (int it = 0; it < 4; it++) {
            int p = it * 16 + warp * 2 + half;     // 0..63
            bool act = (p < SR) && (o < 15);
            int pc  = act ? p : 0;
            int rjc = act ? (p + 1 + o) : 0;       // <= 75 < LR
            float dot = 0.f;
            const uint4* xi = sxh4 + pc * HR4;
            const uint4* xj = sxh4 + rjc * HR4;
#pragma unroll
            for (int k = 0; k < 16; k++) {         // 16 x 8 halves = 128 dims
                uint4 a = xi[k];
                uint4 bb = xj[k];
                const __half2* ah = (const __half2*)&a;
                const __half2* bh = (const __half2*)&bb;
#pragma unroll
                for (int t = 0; t < 4; t++) {
                    float2 af = __half22float2(ah[t]);
                    float2 bf = __half22float2(bh[t]);
                    dot += af.x * bf.x + af.y * bf.y;
                }
            }
            if (act) sdot[p * WIN + o] = dot;
        }
    }
    __syncthreads();

    // ---- Phase C: deg/dinv for DR rows; band values for CR central rows ----
    {
#pragma unroll
        for (int it = 0; it < 6; it++) {
            int gl = it * 8 + warp;                // 0..47
            if (gl >= DR) continue;
            int g = i0 - WIN + gl;
            int sxr = gl + WIN;
            bool valid_i = (g >= 0) && (g < S) && (g < len);
            int spk_i = sspk[sxr];

            int j = g - WIN + lane;
            int sxj = gl + lane;                   // <= 75 < LR for used lanes
            bool inr = (lane < WW) && (j >= 0) && (j < S);

            float dot = 0.f;
            if (lane < WIN) {
                if (j >= 0) dot = sdot[(gl + lane) * WIN + (14 - lane)];
            } else if (lane == WIN) {
                dot = 1.f;                         // exact diagonal
            } else if (lane < WW) {
                dot = sdot[sxr * WIN + (lane - 16)];
            }

            bool valid_j = valid_i && inr && (j < len);
            bool same = valid_j && (sspk[sxj] == spk_i);
            int cnt = __popc(__ballot_sync(0xffffffffu, same));

            float a = 0.f;
            if (valid_j) {
                float c = fminf(fmaxf(dot, -1.f), 1.f);
                a = angular_weight(c) * ((cnt > 1 && same) ? 2.f : 1.f);
            }

            float deg = a;
#pragma unroll
            for (int off = 16; off; off >>= 1)
                deg += __shfl_xor_sync(0xffffffffu, deg, off);

            if (gl >= WIN && gl < WIN + CR && lane < WW)
                sband[(gl - WIN) * WW + lane] = a;
            if (lane == 0)
                sdinv[gl] = (deg > 0.f) ? rsqrtf(deg) : 1.f;
        }
    }
    __syncthreads();

    // ---- Phase D: write the CR band regions (disjoint 32B sectors vs zero role) ----
    {
#pragma unroll
        for (int it = 0; it < 2; it++) {
            int c = it * 8 + warp;                 // 0..15
            int i = i0 + c;
            int jstart = max(i - WIN, 0);
            int jend   = min(i + WIN, S - 1);
            int p0 = jstart & ~7;
            int p1 = (jend & ~7) + 7;
            float di = sdinv[c + WIN];
            float* orow = out + ((size_t)base + i) * S;
#pragma unroll
            for (int pass = 0; pass < 2; pass++) {
                int j2 = p0 + pass * 32 + lane;
                if (j2 <= p1) {
                    int d = j2 - (i - WIN);
                    float v = 0.f;
                    if (d >= 0 && d < WW)
                        v = sband[c * WW + d] * di * sdinv[c + d];
                    orow[j2] = v;
                }
            }
        }
    }
}

extern "C" void kernel_launch(void* const* d_in, const int* in_sizes, int n_in,
                              void* d_out, int out_size) {
    const float* x       = (const float*)d_in[0];
    const float* qmask   = (const float*)d_in[1];
    const int*   dia_len = (const int*)d_in[2];
    float* out = (float*)d_out;

    int B = in_sizes[2];
    int S = in_sizes[0] / (B * DD);
    int NSPK = in_sizes[1] / (B * S);
    int n = B * S;
    int NBAND = (S / CR) * B;

    // one grid, one launch: band blocks first, zero blocks stream behind.
    // No inter-block dependencies; band/zero outputs are disjoint 32B sectors.
    combined_kernel<<<NBAND + n, 256>>>(x, qmask, dia_len, out, B, S, NSPK, NBAND);
}